// round 14
// baseline (speedup 1.0000x reference)
#include <cuda_runtime.h>
#include <math.h>
#include <float.h>
#include <stdint.h>

#define NPTS 16384
#define DIM  512
#define KC   1024
#define KD   (KC * DIM)
#define ITERS 10
#define NTILES 1024            // (NPTS/128) * (KC/128)
#define PGRID  148             // persistent grid = #SMs

// Fixed-point scales for deterministic integer accumulation.
#define SCALE_SUM   4294967296.0      // 2^32
#define SCALE_DIST  68719476736.0     // 2^36

// ---------------- device scratch (no allocations allowed) ----------------
__device__ float              g_centroids[KD];
__device__ float              g_xsq[NPTS];
__device__ float              g_csq[KC];
__device__ unsigned long long g_best[NPTS];  // packed (ordered dist)<<32 | idx
__device__ unsigned long long g_sums[KD];    // fixed-point centroid sums
__device__ int                g_counts[KC];
__device__ unsigned long long g_dacc[KD];    // fixed-point residual^2 sums
__device__ double             g_pA[512];
__device__ double             g_pB[512];
__device__ double             g_pC[512];
__device__ double             g_scal[2];

// k-major transposed operands: g_At[d][n] = feats[n][d], g_Bt[d][k] = centroids[k][d]
__device__ float g_At[DIM * NPTS];
__device__ float g_Bt[DIM * KC];

// ---------------- packed f32x2 helpers (FFMA2 path, PTX-only) ----------------
__device__ __forceinline__ void ffma2(unsigned long long& acc,
                                      unsigned long long a,
                                      unsigned long long b) {
    asm("fma.rn.f32x2 %0, %1, %2, %0;" : "+l"(acc) : "l"(a), "l"(b));
}
__device__ __forceinline__ unsigned long long dup2(float x) {
    unsigned long long r;
    asm("mov.b64 %0, {%1, %1};" : "=l"(r) : "f"(x));
    return r;
}
__device__ __forceinline__ uint32_t smem_u32(const void* p) {
    uint32_t a;
    asm("{ .reg .u64 t; cvta.to.shared.u64 t, %1; cvt.u32.u64 %0, t; }"
        : "=r"(a) : "l"(p));
    return a;
}
__device__ __forceinline__ void cp16(uint32_t dst, const void* src) {
    asm volatile("cp.async.cg.shared.global [%0], [%1], 16;"
                 :: "r"(dst), "l"(src));
}
#define CP_COMMIT()  asm volatile("cp.async.commit_group;" ::: "memory")
#define CP_WAIT1()   asm volatile("cp.async.wait_group 1;" ::: "memory")
#define CP_WAIT0()   asm volatile("cp.async.wait_group 0;" ::: "memory")

// ---------------- exact integer quantization --------------------------------
// Computes __double2ll_rn((double)x * 2^S) bit-exactly with integer ops.
__device__ __forceinline__ long long quantize(float x, int S) {
    unsigned int b = __float_as_uint(x);
    int e = (int)((b >> 23) & 0xFFu);
    long long m = 0;
    if (e != 0) {
        m = (long long)((b & 0x7FFFFFu) | 0x800000u);
        int sh = e - 150 + S;
        if (sh >= 0) {
            m <<= sh;
        } else {
            int s = -sh;
            if (s >= 25) {
                m = 0;
            } else {
                long long fl   = m >> s;
                long long rem  = m & ((1LL << s) - 1);
                long long half = 1LL << (s - 1);
                if (rem > half || (rem == half && (fl & 1))) fl++;
                m = fl;
            }
        }
    }
    return (b & 0x80000000u) ? -m : m;
}

// ---------------- setup kernels ----------------
__global__ void k_transpose_A(const float* __restrict__ feats) {
    __shared__ float t[32][33];
    int bx = blockIdx.x * 32;
    int by = blockIdx.y * 32;
    int tx = threadIdx.x, ty = threadIdx.y;   // (32, 8)
    #pragma unroll
    for (int r = 0; r < 4; r++)
        t[ty + r * 8][tx] = feats[(size_t)(by + ty + r * 8) * DIM + bx + tx];
    __syncthreads();
    #pragma unroll
    for (int r = 0; r < 4; r++)
        g_At[(size_t)(bx + ty + r * 8) * NPTS + by + tx] = t[tx][ty + r * 8];
}
__global__ void k_init_Bt() {
    int i = blockIdx.x * blockDim.x + threadIdx.x;
    if (i >= DIM * KC) return;
    int d = i >> 10, k = i & (KC - 1);
    g_Bt[(size_t)d * KC + k] = g_At[(size_t)d * NPTS + k];
}
__global__ void k_init_csq() {
    int i = blockIdx.x * blockDim.x + threadIdx.x;
    if (i < KC) g_csq[i] = g_xsq[i];
}
__global__ void k_copy_init(const float* __restrict__ feats) {
    int i = blockIdx.x * blockDim.x + threadIdx.x;
    if (i < KD) g_centroids[i] = feats[i];
}

// ---------------- row squared norms ----------------
__global__ void k_xsq(const float* __restrict__ feats) {
    int w    = (blockIdx.x * blockDim.x + threadIdx.x) >> 5;
    int lane = threadIdx.x & 31;
    if (w >= NPTS) return;
    const float* r = feats + (size_t)w * DIM;
    float s = 0.f;
    #pragma unroll
    for (int i = 0; i < DIM / 32; i++) { float v = r[lane + i * 32]; s += v * v; }
    #pragma unroll
    for (int o = 16; o; o >>= 1) s += __shfl_xor_sync(0xffffffffu, s, o);
    if (lane == 0) g_xsq[w] = s;
}

// ---------------- one-time / final clears ----------------
__global__ void k_clear() {
    int i = blockIdx.x * blockDim.x + threadIdx.x;   // grid covers KD
    g_sums[i] = 0ull;
    if (i < NPTS) g_best[i] = 0xFFFFFFFFFFFFFFFFull;
    if (i < KC)   g_counts[i] = 0;
}
__global__ void k_clear_final() {
    int i = blockIdx.x * blockDim.x + threadIdx.x;   // grid covers KD
    g_dacc[i] = 0ull;
    if (i < NPTS) g_best[i] = 0xFFFFFFFFFFFFFFFFull;
}

// ---------------- persistent fused distance-GEMM + argmin ------------------
// grid (148, 1), 512 threads, 1 CTA/SM. Each CTA loops tiles t += 148.
// Tile: 128 points x 128 clusters. Per-thread 8 rows (4 f32x2 pairs) x 4 cols.
// FFMA2 chain per (row,col) identical to prior rounds -> bit-identical dots.
__global__ __launch_bounds__(512, 1)
void k_assign(void) {
    __shared__ float As[2][16][128];
    __shared__ float Bs[2][16][128];

    int tid  = threadIdx.x;
    int tx   = tid & 31;       // col group: cols tx*4 .. tx*4+3
    int ty   = tid >> 5;       // row group: rows ty*8 .. ty*8+7
    int frow = tid >> 5;       // fill row 0..15
    int fs   = tid & 31;       // fill 16B segment 0..31

    int t = blockIdx.x;
    if (t < NTILES) {
        int m0 = (t >> 3) * 128, nbase = (t & 7) * 128;
        uint32_t aD = smem_u32(&As[0][frow][fs * 4]);
        uint32_t bD = smem_u32(&Bs[0][frow][fs * 4]);
        cp16(aD, g_At + (size_t)frow * NPTS + m0 + fs * 4);
        cp16(bD, g_Bt + (size_t)frow * KC + nbase + fs * 4);
        CP_COMMIT();
    }

    for (; t < NTILES; t += PGRID) {
        int m0    = (t >> 3) * 128;
        int nbase = (t & 7) * 128;
        int tn    = t + PGRID;
        int has_next = (tn < NTILES);
        int nm0 = 0, nnb = 0;
        if (has_next) { nm0 = (tn >> 3) * 128; nnb = (tn & 7) * 128; }

        float xr[8];
        #pragma unroll
        for (int i = 0; i < 8; i++) xr[i] = g_xsq[m0 + ty * 8 + i];

        unsigned long long acc2[4][4];
        #pragma unroll
        for (int p = 0; p < 4; p++)
            #pragma unroll
            for (int j = 0; j < 4; j++) acc2[p][j] = 0ull;

        for (int c = 0; c < 32; ++c) {
            int buf = c & 1;
            if (c + 1 < 32) {
                int k1 = (c + 1) * 16;
                uint32_t aD = smem_u32(&As[buf ^ 1][frow][fs * 4]);
                uint32_t bD = smem_u32(&Bs[buf ^ 1][frow][fs * 4]);
                cp16(aD, g_At + (size_t)(k1 + frow) * NPTS + m0 + fs * 4);
                cp16(bD, g_Bt + (size_t)(k1 + frow) * KC + nbase + fs * 4);
                CP_COMMIT();
                CP_WAIT1();
            } else if (has_next) {
                // prefetch next tile's chunk 0 into buf 0 (chunk30's compute
                // finished before c=31; epilogue never touches smem)
                uint32_t aD = smem_u32(&As[0][frow][fs * 4]);
                uint32_t bD = smem_u32(&Bs[0][frow][fs * 4]);
                cp16(aD, g_At + (size_t)frow * NPTS + nm0 + fs * 4);
                cp16(bD, g_Bt + (size_t)frow * KC + nnb + fs * 4);
                CP_COMMIT();
                CP_WAIT1();    // ensures chunk 31 arrived
            } else {
                CP_WAIT0();
            }
            __syncthreads();

            #pragma unroll
            for (int kk = 0; kk < 16; kk++) {
                unsigned long long a2[4];
                #pragma unroll
                for (int p = 0; p < 4; p++)
                    a2[p] = *(const unsigned long long*)&As[buf][kk][ty * 8 + 2 * p];
                float4 bv = *(const float4*)&Bs[buf][kk][tx * 4];
                float b4[4] = {bv.x, bv.y, bv.z, bv.w};
                #pragma unroll
                for (int j = 0; j < 4; j++) {
                    unsigned long long bd = dup2(b4[j]);
                    #pragma unroll
                    for (int p = 0; p < 4; p++) ffma2(acc2[p][j], a2[p], bd);
                }
            }
            __syncthreads();
        }

        // distances + argmin: per-thread cols tx*4+j ascend with j ->
        // strict < keeps first-min semantics.
        float best[8];
        int   bidx[8];
        #pragma unroll
        for (int i = 0; i < 8; i++) { best[i] = FLT_MAX; bidx[i] = 0; }

        #pragma unroll
        for (int j = 0; j < 4; j++) {
            int col = nbase + tx * 4 + j;
            float cs = g_csq[col];
            #pragma unroll
            for (int p = 0; p < 4; p++) {
                float d0, d1;
                asm("mov.b64 {%0, %1}, %2;" : "=f"(d0), "=f"(d1) : "l"(acc2[p][j]));
                float dist0 = xr[2 * p]     - 2.0f * d0 + cs;
                float dist1 = xr[2 * p + 1] - 2.0f * d1 + cs;
                if (dist0 < best[2 * p])     { best[2 * p]     = dist0; bidx[2 * p]     = col; }
                if (dist1 < best[2 * p + 1]) { best[2 * p + 1] = dist1; bidx[2 * p + 1] = col; }
            }
        }

        // reduce across the 32 lanes (lane cols ascend with tx -> idx
        // tie-break reproduces global first-min), then cross-tile atomicMin.
        #pragma unroll
        for (int i = 0; i < 8; i++) {
            float bv = best[i];
            int   bi = bidx[i];
            #pragma unroll
            for (int o = 16; o; o >>= 1) {
                float ov = __shfl_xor_sync(0xffffffffu, bv, o);
                int   oi = __shfl_xor_sync(0xffffffffu, bi, o);
                if (ov < bv || (ov == bv && oi < bi)) { bv = ov; bi = oi; }
            }
            if (tx == 0) {
                unsigned int u = __float_as_uint(bv);
                u = (u & 0x80000000u) ? ~u : (u | 0x80000000u);
                unsigned long long key = ((unsigned long long)u << 32) |
                                         (unsigned int)bi;
                atomicMin(&g_best[m0 + ty * 8 + i], key);
            }
        }
    }
}

// ---------------- deterministic segment sums (int quantize + atomics) ------
__global__ void k_accum(const float* __restrict__ feats) {
    int p = blockIdx.x;
    int c = (int)(unsigned int)(g_best[p] & 0xFFFFFFFFull);
    const float* f = feats + (size_t)p * DIM;
    unsigned long long* srow = g_sums + (size_t)c * DIM;
    for (int d = threadIdx.x; d < DIM; d += blockDim.x) {
        long long q = quantize(f[d], 32);
        atomicAdd(&srow[d], (unsigned long long)q);
    }
    if (threadIdx.x == 0) atomicAdd(&g_counts[c], 1);
}

// ---------------- fused centroid update + Bt + csq + next-iter clears ------
__global__ __launch_bounds__(128)
void k_update(void) {
    __shared__ float  sc[DIM];
    __shared__ double sinv;
    int c = blockIdx.x, t = threadIdx.x;
    int cnt = g_counts[c];
    if (t == 0) sinv = 1.0 / (double)(cnt > 0 ? cnt : 1);
    __syncthreads();

    size_t base = (size_t)c * DIM + t * 4;
    float v[4];
    if (cnt > 0) {
        double inv = sinv;
        #pragma unroll
        for (int j = 0; j < 4; j++) {
            long long s = (long long)g_sums[base + j];
            v[j] = (float)((double)s * (1.0 / SCALE_SUM) * inv);
        }
        *(float4*)(g_centroids + base) = make_float4(v[0], v[1], v[2], v[3]);
    } else {
        float4 old = *(const float4*)(g_centroids + base);
        v[0] = old.x; v[1] = old.y; v[2] = old.z; v[3] = old.w;
    }
    // clears for the next iteration (after reads)
    #pragma unroll
    for (int j = 0; j < 4; j++) g_sums[base + j] = 0ull;
    if (t == 0) g_counts[c] = 0;
    if (t < NPTS / KC) g_best[c * (NPTS / KC) + t] = 0xFFFFFFFFFFFFFFFFull;

    #pragma unroll
    for (int j = 0; j < 4; j++) {
        sc[t * 4 + j] = v[j];
        g_Bt[(size_t)(t * 4 + j) * KC + c] = v[j];
    }
    __syncthreads();

    // csq with the EXACT lane-major summation order of the original k_csq
    if (t < 32) {
        float s = 0.f;
        #pragma unroll
        for (int i = 0; i < DIM / 32; i++) { float vv = sc[t + i * 32]; s += vv * vv; }
        #pragma unroll
        for (int o = 16; o; o >>= 1) s += __shfl_xor_sync(0xffffffffu, s, o);
        if (t == 0) g_csq[c] = s;
    }
}

// ---------------- residual^2 sums (int quantize + atomics) -----------------
__global__ void k_resid(const float* __restrict__ feats) {
    int p = blockIdx.x;
    int c = (int)(unsigned int)(g_best[p] & 0xFFFFFFFFull);
    const float* f  = feats + (size_t)p * DIM;
    const float* cc = g_centroids + (size_t)c * DIM;
    unsigned long long* drow = g_dacc + (size_t)c * DIM;
    for (int d = threadIdx.x; d < DIM; d += blockDim.x) {
        float r  = f[d] - cc[d];
        float r2 = r * r;
        long long q = quantize(r2, 36);
        atomicAdd(&drow[d], (unsigned long long)q);
    }
}

// ---------------- final reductions (unchanged) ----------------
__global__ void k_reduce1() {
    __shared__ double sa[256], sb[256];
    int t    = threadIdx.x;
    int base = blockIdx.x * 1024;
    double la = 0.0, lb = 0.0;
    #pragma unroll
    for (int e = 0; e < 4; e++) {
        int i = base + t + e * 256;
        float dist = (float)((double)(long long)g_dacc[i] * (1.0 / SCALE_DIST));
        float p1 = expf(dist * -10.0f);
        float p2 = expf(dist * -10.0f);
        la += (double)p1;
        lb += (double)logf(p2 + 1e-6f);
    }
    sa[t] = la; sb[t] = lb;
    __syncthreads();
    for (int s = 128; s; s >>= 1) {
        if (t < s) { sa[t] += sa[t + s]; sb[t] += sb[t + s]; }
        __syncthreads();
    }
    if (t == 0) { g_pA[blockIdx.x] = sa[0]; g_pB[blockIdx.x] = sb[0]; }
}
__global__ void k_final1() {
    __shared__ double sa[512], sb[512];
    int t = threadIdx.x;
    sa[t] = g_pA[t]; sb[t] = g_pB[t];
    __syncthreads();
    for (int s = 256; s; s >>= 1) {
        if (t < s) { sa[t] += sa[t + s]; sb[t] += sb[t + s]; }
        __syncthreads();
    }
    if (t == 0) { g_scal[0] = sa[0]; g_scal[1] = sb[0]; }
}
__global__ void k_reduce2() {
    __shared__ double sc[256];
    int t    = threadIdx.x;
    int base = blockIdx.x * 1024;
    float S  = (float)g_scal[0];
    double lc = 0.0;
    #pragma unroll
    for (int e = 0; e < 4; e++) {
        int i = base + t + e * 256;
        float dist = (float)((double)(long long)g_dacc[i] * (1.0 / SCALE_DIST));
        float p1 = expf(dist * -10.0f);
        float q  = p1 / S;
        lc += (double)(q * logf(q + 1e-6f));
    }
    sc[t] = lc;
    __syncthreads();
    for (int s = 128; s; s >>= 1) {
        if (t < s) sc[t] += sc[t + s];
        __syncthreads();
    }
    if (t == 0) g_pC[blockIdx.x] = sc[0];
}
__global__ void k_final2(float* __restrict__ out) {
    __shared__ double sc[512];
    int t = threadIdx.x;
    sc[t] = g_pC[t];
    __syncthreads();
    for (int s = 256; s; s >>= 1) {
        if (t < s) sc[t] += sc[t + s];
        __syncthreads();
    }
    if (t == 0) {
        double ent = sc[0] / (double)KD;
        double nll = -(g_scal[1] / (double)KD);
        out[0] = (float)(ent + nll);
    }
}

// ---------------- launch ----------------
extern "C" void kernel_launch(void* const* d_in, const int* in_sizes, int n_in,
                              void* d_out, int out_size) {
    (void)in_sizes; (void)n_in; (void)out_size;
    const float* feats = (const float*)d_in[0];
    float* out = (float*)d_out;

    dim3 tb(32, 8);
    k_xsq<<<NPTS / 8, 256>>>(feats);
    k_copy_init<<<KD / 256, 256>>>(feats);
    k_transpose_A<<<dim3(DIM / 32, NPTS / 32), tb>>>(feats);
    k_init_Bt<<<(DIM * KC) / 256, 256>>>();
    k_init_csq<<<KC / 256, 256>>>();
    k_clear<<<KD / 256, 256>>>();

    for (int it = 0; it < ITERS; ++it) {
        k_assign<<<PGRID, 512>>>();
        k_accum<<<NPTS, 128>>>(feats);
        k_update<<<KC, 128>>>();       // also clears sums/counts/best
    }

    k_clear_final<<<KD / 256, 256>>>();
    k_assign<<<PGRID, 512>>>();
    k_resid<<<NPTS, 128>>>(feats);

    k_reduce1<<<512, 256>>>();
    k_final1<<<1, 512>>>();
    k_reduce2<<<512, 256>>>();
    k_final2<<<1, 512>>>(out);
}

// round 15
// speedup vs baseline: 1.0650x; 1.0650x over previous
#include <cuda_runtime.h>
#include <math.h>
#include <float.h>
#include <stdint.h>

#define NPTS 16384
#define DIM  512
#define KC   1024
#define KD   (KC * DIM)
#define ITERS 10
#define NTILES 1024            // (NPTS/128) * (KC/128)
#define PGRID  296             // persistent grid = 2 CTAs per SM

// Fixed-point scales for deterministic integer accumulation.
#define SCALE_SUM   4294967296.0      // 2^32
#define SCALE_DIST  68719476736.0     // 2^36

// ---------------- device scratch (no allocations allowed) ----------------
__device__ float              g_centroids[KD];
__device__ float              g_xsq[NPTS];
__device__ float              g_csq[KC];
__device__ unsigned long long g_best[NPTS];  // packed (ordered dist)<<32 | idx
__device__ unsigned long long g_sums[KD];    // fixed-point centroid sums
__device__ int                g_counts[KC];
__device__ unsigned long long g_dacc[KD];    // fixed-point residual^2 sums
__device__ double             g_pA[512];
__device__ double             g_pB[512];
__device__ double             g_pC[512];
__device__ double             g_scal[2];

// k-major transposed operands: g_At[d][n] = feats[n][d], g_Bt[d][k] = centroids[k][d]
__device__ float g_At[DIM * NPTS];
__device__ float g_Bt[DIM * KC];

// ---------------- packed f32x2 helpers (FFMA2 path, PTX-only) ----------------
__device__ __forceinline__ void ffma2(unsigned long long& acc,
                                      unsigned long long a,
                                      unsigned long long b) {
    asm("fma.rn.f32x2 %0, %1, %2, %0;" : "+l"(acc) : "l"(a), "l"(b));
}
__device__ __forceinline__ unsigned long long dup2(float x) {
    unsigned long long r;
    asm("mov.b64 %0, {%1, %1};" : "=l"(r) : "f"(x));
    return r;
}
__device__ __forceinline__ uint32_t smem_u32(const void* p) {
    uint32_t a;
    asm("{ .reg .u64 t; cvta.to.shared.u64 t, %1; cvt.u32.u64 %0, t; }"
        : "=r"(a) : "l"(p));
    return a;
}
__device__ __forceinline__ void cp16(uint32_t dst, const void* src) {
    asm volatile("cp.async.cg.shared.global [%0], [%1], 16;"
                 :: "r"(dst), "l"(src));
}
#define CP_COMMIT()  asm volatile("cp.async.commit_group;" ::: "memory")
#define CP_WAIT1()   asm volatile("cp.async.wait_group 1;" ::: "memory")
#define CP_WAIT0()   asm volatile("cp.async.wait_group 0;" ::: "memory")

// ---------------- exact integer quantization --------------------------------
// Computes __double2ll_rn((double)x * 2^S) bit-exactly with integer ops.
__device__ __forceinline__ long long quantize(float x, int S) {
    unsigned int b = __float_as_uint(x);
    int e = (int)((b >> 23) & 0xFFu);
    long long m = 0;
    if (e != 0) {
        m = (long long)((b & 0x7FFFFFu) | 0x800000u);
        int sh = e - 150 + S;
        if (sh >= 0) {
            m <<= sh;
        } else {
            int s = -sh;
            if (s >= 25) {
                m = 0;
            } else {
                long long fl   = m >> s;
                long long rem  = m & ((1LL << s) - 1);
                long long half = 1LL << (s - 1);
                if (rem > half || (rem == half && (fl & 1))) fl++;
                m = fl;
            }
        }
    }
    return (b & 0x80000000u) ? -m : m;
}

// ---------------- setup kernels ----------------
__global__ void k_transpose_A(const float* __restrict__ feats) {
    __shared__ float t[32][33];
    int bx = blockIdx.x * 32;
    int by = blockIdx.y * 32;
    int tx = threadIdx.x, ty = threadIdx.y;   // (32, 8)
    #pragma unroll
    for (int r = 0; r < 4; r++)
        t[ty + r * 8][tx] = feats[(size_t)(by + ty + r * 8) * DIM + bx + tx];
    __syncthreads();
    #pragma unroll
    for (int r = 0; r < 4; r++)
        g_At[(size_t)(bx + ty + r * 8) * NPTS + by + tx] = t[tx][ty + r * 8];
}
__global__ void k_init_Bt() {
    int i = blockIdx.x * blockDim.x + threadIdx.x;
    if (i >= DIM * KC) return;
    int d = i >> 10, k = i & (KC - 1);
    g_Bt[(size_t)d * KC + k] = g_At[(size_t)d * NPTS + k];
}
__global__ void k_init_csq() {
    int i = blockIdx.x * blockDim.x + threadIdx.x;
    if (i < KC) g_csq[i] = g_xsq[i];
}
__global__ void k_copy_init(const float* __restrict__ feats) {
    int i = blockIdx.x * blockDim.x + threadIdx.x;
    if (i < KD) g_centroids[i] = feats[i];
}

// ---------------- row squared norms ----------------
__global__ void k_xsq(const float* __restrict__ feats) {
    int w    = (blockIdx.x * blockDim.x + threadIdx.x) >> 5;
    int lane = threadIdx.x & 31;
    if (w >= NPTS) return;
    const float* r = feats + (size_t)w * DIM;
    float s = 0.f;
    #pragma unroll
    for (int i = 0; i < DIM / 32; i++) { float v = r[lane + i * 32]; s += v * v; }
    #pragma unroll
    for (int o = 16; o; o >>= 1) s += __shfl_xor_sync(0xffffffffu, s, o);
    if (lane == 0) g_xsq[w] = s;
}

// ---------------- one-time / final clears ----------------
__global__ void k_clear() {
    int i = blockIdx.x * blockDim.x + threadIdx.x;   // grid covers KD
    g_sums[i] = 0ull;
    if (i < NPTS) g_best[i] = 0xFFFFFFFFFFFFFFFFull;
    if (i < KC)   g_counts[i] = 0;
}
__global__ void k_clear_final() {
    int i = blockIdx.x * blockDim.x + threadIdx.x;   // grid covers KD
    g_dacc[i] = 0ull;
    if (i < NPTS) g_best[i] = 0xFFFFFFFFFFFFFFFFull;
}

// ---------------- persistent fused distance-GEMM + argmin ------------------
// grid (296), 256 threads, 2 CTAs/SM (dual-CTA barrier interleave preserved).
// Each CTA loops tiles t += 296; per-tile body identical to the proven R11
// kernel (bit-identical FFMA2/argmin chain). Next tile's chunk 0 prefetched.
__global__ __launch_bounds__(256, 2)
void k_assign(void) {
    __shared__ float As[2][16][128];
    __shared__ float Bs[2][16][128];

    int tid  = threadIdx.x;
    int tx   = tid & 15;
    int ty   = tid >> 4;
    int frow = tid >> 4;
    int fs   = (tid & 15) * 2;

    int t = blockIdx.x;
    if (t < NTILES) {
        int m0 = (t >> 3) * 128, nbase = (t & 7) * 128;
        uint32_t aD = smem_u32(&As[0][frow][fs * 4]);
        uint32_t bD = smem_u32(&Bs[0][frow][fs * 4]);
        const float* asrc = g_At + (size_t)frow * NPTS + m0 + fs * 4;
        const float* bsrc = g_Bt + (size_t)frow * KC + nbase + fs * 4;
        cp16(aD, asrc);      cp16(aD + 16, asrc + 4);
        cp16(bD, bsrc);      cp16(bD + 16, bsrc + 4);
        CP_COMMIT();
    }

    for (; t < NTILES; t += PGRID) {
        int m0    = (t >> 3) * 128;
        int nbase = (t & 7) * 128;
        int tn    = t + PGRID;
        int has_next = (tn < NTILES);
        int nm0 = 0, nnb = 0;
        if (has_next) { nm0 = (tn >> 3) * 128; nnb = (tn & 7) * 128; }

        float xr[8];
        #pragma unroll
        for (int i = 0; i < 8; i++) xr[i] = g_xsq[m0 + ty * 8 + i];

        unsigned long long acc2[4][8];
        #pragma unroll
        for (int p = 0; p < 4; p++)
            #pragma unroll
            for (int j = 0; j < 8; j++) acc2[p][j] = 0ull;

        for (int c = 0; c < 32; ++c) {
            int buf = c & 1;
            if (c + 1 < 32) {
                int k1 = (c + 1) * 16;
                uint32_t aD = smem_u32(&As[buf ^ 1][frow][fs * 4]);
                uint32_t bD = smem_u32(&Bs[buf ^ 1][frow][fs * 4]);
                const float* asrc = g_At + (size_t)(k1 + frow) * NPTS + m0 + fs * 4;
                const float* bsrc = g_Bt + (size_t)(k1 + frow) * KC + nbase + fs * 4;
                cp16(aD, asrc);      cp16(aD + 16, asrc + 4);
                cp16(bD, bsrc);      cp16(bD + 16, bsrc + 4);
                CP_COMMIT();
                CP_WAIT1();
            } else if (has_next) {
                // prefetch next tile's chunk 0 into buf 0: the trailing
                // __syncthreads of c=30 guarantees buf 0's compute is done;
                // the epilogue below never touches smem.
                uint32_t aD = smem_u32(&As[0][frow][fs * 4]);
                uint32_t bD = smem_u32(&Bs[0][frow][fs * 4]);
                const float* asrc = g_At + (size_t)frow * NPTS + nm0 + fs * 4;
                const float* bsrc = g_Bt + (size_t)frow * KC + nnb + fs * 4;
                cp16(aD, asrc);      cp16(aD + 16, asrc + 4);
                cp16(bD, bsrc);      cp16(bD + 16, bsrc + 4);
                CP_COMMIT();
                CP_WAIT1();          // chunk 31 arrived, prefetch in flight
            } else {
                CP_WAIT0();
            }
            __syncthreads();

            #pragma unroll
            for (int kk = 0; kk < 16; kk++) {
                unsigned long long a2[4];
                #pragma unroll
                for (int p = 0; p < 4; p++)
                    a2[p] = *(const unsigned long long*)&As[buf][kk][ty * 8 + 2 * p];
                float4 bv0 = *(const float4*)&Bs[buf][kk][tx * 4];
                float4 bv1 = *(const float4*)&Bs[buf][kk][64 + tx * 4];
                float bv[8] = {bv0.x, bv0.y, bv0.z, bv0.w,
                               bv1.x, bv1.y, bv1.z, bv1.w};
                #pragma unroll
                for (int j = 0; j < 8; j++) {
                    unsigned long long bd = dup2(bv[j]);
                    #pragma unroll
                    for (int p = 0; p < 4; p++) ffma2(acc2[p][j], a2[p], bd);
                }
            }
            __syncthreads();
        }

        // distances + argmin (identical chain to R11)
        float best[8];
        int   bidx[8];
        #pragma unroll
        for (int i = 0; i < 8; i++) { best[i] = FLT_MAX; bidx[i] = 0; }

        #pragma unroll
        for (int j = 0; j < 8; j++) {
            int col = nbase + ((j < 4) ? (tx * 4 + j) : (64 + tx * 4 + (j - 4)));
            float cs = g_csq[col];
            #pragma unroll
            for (int p = 0; p < 4; p++) {
                float d0, d1;
                asm("mov.b64 {%0, %1}, %2;" : "=f"(d0), "=f"(d1) : "l"(acc2[p][j]));
                float dist0 = xr[2 * p]     - 2.0f * d0 + cs;
                float dist1 = xr[2 * p + 1] - 2.0f * d1 + cs;
                if (dist0 < best[2 * p])     { best[2 * p]     = dist0; bidx[2 * p]     = col; }
                if (dist1 < best[2 * p + 1]) { best[2 * p + 1] = dist1; bidx[2 * p + 1] = col; }
            }
        }

        #pragma unroll
        for (int i = 0; i < 8; i++) {
            float bv = best[i];
            int   bi = bidx[i];
            #pragma unroll
            for (int o = 8; o; o >>= 1) {
                float ov = __shfl_xor_sync(0xffffffffu, bv, o);
                int   oi = __shfl_xor_sync(0xffffffffu, bi, o);
                if (ov < bv || (ov == bv && oi < bi)) { bv = ov; bi = oi; }
            }
            if (tx == 0) {
                unsigned int u = __float_as_uint(bv);
                u = (u & 0x80000000u) ? ~u : (u | 0x80000000u);
                unsigned long long key = ((unsigned long long)u << 32) |
                                         (unsigned int)bi;
                atomicMin(&g_best[m0 + ty * 8 + i], key);
            }
        }
    }
}

// ---------------- deterministic segment sums (int quantize + atomics) ------
__global__ void k_accum(const float* __restrict__ feats) {
    int p = blockIdx.x;
    int c = (int)(unsigned int)(g_best[p] & 0xFFFFFFFFull);
    const float* f = feats + (size_t)p * DIM;
    unsigned long long* srow = g_sums + (size_t)c * DIM;
    for (int d = threadIdx.x; d < DIM; d += blockDim.x) {
        long long q = quantize(f[d], 32);
        atomicAdd(&srow[d], (unsigned long long)q);
    }
    if (threadIdx.x == 0) atomicAdd(&g_counts[c], 1);
}

// ---------------- fused centroid update + Bt + csq + next-iter clears ------
__global__ __launch_bounds__(128)
void k_update(void) {
    __shared__ float  sc[DIM];
    __shared__ double sinv;
    int c = blockIdx.x, t = threadIdx.x;
    int cnt = g_counts[c];
    if (t == 0) sinv = 1.0 / (double)(cnt > 0 ? cnt : 1);
    __syncthreads();

    size_t base = (size_t)c * DIM + t * 4;
    float v[4];
    if (cnt > 0) {
        double inv = sinv;
        #pragma unroll
        for (int j = 0; j < 4; j++) {
            long long s = (long long)g_sums[base + j];
            v[j] = (float)((double)s * (1.0 / SCALE_SUM) * inv);
        }
        *(float4*)(g_centroids + base) = make_float4(v[0], v[1], v[2], v[3]);
    } else {
        float4 old = *(const float4*)(g_centroids + base);
        v[0] = old.x; v[1] = old.y; v[2] = old.z; v[3] = old.w;
    }
    // clears for the next iteration (after reads)
    #pragma unroll
    for (int j = 0; j < 4; j++) g_sums[base + j] = 0ull;
    if (t == 0) g_counts[c] = 0;
    if (t < NPTS / KC) g_best[c * (NPTS / KC) + t] = 0xFFFFFFFFFFFFFFFFull;

    #pragma unroll
    for (int j = 0; j < 4; j++) {
        sc[t * 4 + j] = v[j];
        g_Bt[(size_t)(t * 4 + j) * KC + c] = v[j];
    }
    __syncthreads();

    // csq with the EXACT lane-major summation order of the original k_csq
    if (t < 32) {
        float s = 0.f;
        #pragma unroll
        for (int i = 0; i < DIM / 32; i++) { float vv = sc[t + i * 32]; s += vv * vv; }
        #pragma unroll
        for (int o = 16; o; o >>= 1) s += __shfl_xor_sync(0xffffffffu, s, o);
        if (t == 0) g_csq[c] = s;
    }
}

// ---------------- residual^2 sums (int quantize + atomics) -----------------
__global__ void k_resid(const float* __restrict__ feats) {
    int p = blockIdx.x;
    int c = (int)(unsigned int)(g_best[p] & 0xFFFFFFFFull);
    const float* f  = feats + (size_t)p * DIM;
    const float* cc = g_centroids + (size_t)c * DIM;
    unsigned long long* drow = g_dacc + (size_t)c * DIM;
    for (int d = threadIdx.x; d < DIM; d += blockDim.x) {
        float r  = f[d] - cc[d];
        float r2 = r * r;
        long long q = quantize(r2, 36);
        atomicAdd(&drow[d], (unsigned long long)q);
    }
}

// ---------------- final reductions (unchanged) ----------------
__global__ void k_reduce1() {
    __shared__ double sa[256], sb[256];
    int t    = threadIdx.x;
    int base = blockIdx.x * 1024;
    double la = 0.0, lb = 0.0;
    #pragma unroll
    for (int e = 0; e < 4; e++) {
        int i = base + t + e * 256;
        float dist = (float)((double)(long long)g_dacc[i] * (1.0 / SCALE_DIST));
        float p1 = expf(dist * -10.0f);
        float p2 = expf(dist * -10.0f);
        la += (double)p1;
        lb += (double)logf(p2 + 1e-6f);
    }
    sa[t] = la; sb[t] = lb;
    __syncthreads();
    for (int s = 128; s; s >>= 1) {
        if (t < s) { sa[t] += sa[t + s]; sb[t] += sb[t + s]; }
        __syncthreads();
    }
    if (t == 0) { g_pA[blockIdx.x] = sa[0]; g_pB[blockIdx.x] = sb[0]; }
}
__global__ void k_final1() {
    __shared__ double sa[512], sb[512];
    int t = threadIdx.x;
    sa[t] = g_pA[t]; sb[t] = g_pB[t];
    __syncthreads();
    for (int s = 256; s; s >>= 1) {
        if (t < s) { sa[t] += sa[t + s]; sb[t] += sb[t + s]; }
        __syncthreads();
    }
    if (t == 0) { g_scal[0] = sa[0]; g_scal[1] = sb[0]; }
}
__global__ void k_reduce2() {
    __shared__ double sc[256];
    int t    = threadIdx.x;
    int base = blockIdx.x * 1024;
    float S  = (float)g_scal[0];
    double lc = 0.0;
    #pragma unroll
    for (int e = 0; e < 4; e++) {
        int i = base + t + e * 256;
        float dist = (float)((double)(long long)g_dacc[i] * (1.0 / SCALE_DIST));
        float p1 = expf(dist * -10.0f);
        float q  = p1 / S;
        lc += (double)(q * logf(q + 1e-6f));
    }
    sc[t] = lc;
    __syncthreads();
    for (int s = 128; s; s >>= 1) {
        if (t < s) sc[t] += sc[t + s];
        __syncthreads();
    }
    if (t == 0) g_pC[blockIdx.x] = sc[0];
}
__global__ void k_final2(float* __restrict__ out) {
    __shared__ double sc[512];
    int t = threadIdx.x;
    sc[t] = g_pC[t];
    __syncthreads();
    for (int s = 256; s; s >>= 1) {
        if (t < s) sc[t] += sc[t + s];
        __syncthreads();
    }
    if (t == 0) {
        double ent = sc[0] / (double)KD;
        double nll = -(g_scal[1] / (double)KD);
        out[0] = (float)(ent + nll);
    }
}

// ---------------- launch ----------------
extern "C" void kernel_launch(void* const* d_in, const int* in_sizes, int n_in,
                              void* d_out, int out_size) {
    (void)in_sizes; (void)n_in; (void)out_size;
    const float* feats = (const float*)d_in[0];
    float* out = (float*)d_out;

    dim3 tb(32, 8);
    k_xsq<<<NPTS / 8, 256>>>(feats);
    k_copy_init<<<KD / 256, 256>>>(feats);
    k_transpose_A<<<dim3(DIM / 32, NPTS / 32), tb>>>(feats);
    k_init_Bt<<<(DIM * KC) / 256, 256>>>();
    k_init_csq<<<KC / 256, 256>>>();
    k_clear<<<KD / 256, 256>>>();

    for (int it = 0; it < ITERS; ++it) {
        k_assign<<<PGRID, 256>>>();
        k_accum<<<NPTS, 128>>>(feats);
        k_update<<<KC, 128>>>();       // also clears sums/counts/best
    }

    k_clear_final<<<KD / 256, 256>>>();
    k_assign<<<PGRID, 256>>>();
    k_resid<<<NPTS, 128>>>(feats);

    k_reduce1<<<512, 256>>>();
    k_final1<<<1, 512>>>();
    k_reduce2<<<512, 256>>>();
    k_final2<<<1, 512>>>(out);
}